// round 15
// baseline (speedup 1.0000x reference)
#include <cuda_runtime.h>
#include <cuda_fp16.h>
#include <cstdint>

// ---------------------------------------------------------------------------
// FNO on sm_103a. Circulant Fourier layers via a 2KB reversed-g pair table:
// B[k][n] = g[(n-k-3) mod 256]. Uncropped circulant rows k=253..255 ARE the
// x-term coefficients, so x0..x2 live in h's k-columns 253..255 and the MMA
// computes conv + x-term together. True h[253..255] in a 1KB side array.
//   h0 = relu(mu @ W1 + b1)           (W1 via one-shot cp.async, ldsm path)
//   h  = relu(circ_g([h|x]) + h*lw)   l=0..3
//   out = h @ W2 + b2                 (fused into stage-4 epilogue, fp32)
// R15 = R14 with CORRECT circular-window algebra: slot(ks,j) = (j+7ks)%9
// (in-place v_{ks+1}[j]=v_ks[j-2] requires slot shift of -2 == +7 mod 9);
// new values prefetched into temps, committed after their slot's last use.
// h double-buffered (W1 overlays bufB); epilogue inlined into last K-slice.
// 256 threads, 64 rows/CTA, 83KB SMEM -> 2 CTAs/SM. No weight streaming.
// ---------------------------------------------------------------------------

#define NMODES 256
#define NLAYERS 4
#define MROWS 64
#define NTHREADS 256
#define HW 132                              // h row stride in 32-bit words
#define H_BYTES (MROWS * HW * 4)            // 33792
#define H0_OFF  0
#define H1_OFF  H_BYTES                     // W1 image overlays this
#define T2_OFF  (H1_OFF + H_BYTES)          // 67584: 4 x 2048B pair tables
#define LW_OFF  (T2_OFF + NLAYERS * 2048)   // 75776
#define B1_OFF  (LW_OFF + NLAYERS * NMODES * 4) // 79872
#define XS_OFF  (B1_OFF + NMODES * 4)       // 80896
#define W2S_OFF (XS_OFF + MROWS * 4 * 4)    // 81920
#define DEC_OFF (W2S_OFF + NMODES * 4)      // 82944
#define HS_OFF  (DEC_OFF + MROWS * 4 * 4)   // 83968
#define SMEM_TOTAL (HS_OFF + MROWS * 4 * 4) // 84992

__device__ float g_dev[NLAYERS * NMODES];
__device__ __align__(16) uint32_t t2_dev[NLAYERS * 512]; // half2 pair tables
__device__ __align__(16) __half w1sw_dev[NMODES * 64];   // swizzled W1^T image

__device__ __forceinline__ uint32_t smem_u32(const void* p) {
    uint32_t a;
    asm("{ .reg .u64 t; cvta.to.shared.u64 t, %1; cvt.u32.u64 %0, t; }" : "=r"(a) : "l"(p));
    return a;
}

#define CP_ASYNC16(dst, src) \
    asm volatile("cp.async.cg.shared.global [%0], [%1], 16;" :: "r"(dst), "l"(src) : "memory")
#define CP_COMMIT() asm volatile("cp.async.commit_group;" ::: "memory")
#define CP_WAIT0()  asm volatile("cp.async.wait_group 0;" ::: "memory")

#define LDS_B(dst, base, imm) \
    asm volatile("ld.shared.b32 %0, [%1+%2];" : "=r"(dst) : "r"(base), "n"(imm))

// group barrier: warps 0-3 (wm=0) use barrier 1, warps 4-7 (wm=1) barrier 2
#define BAR_GROUP() \
    asm volatile("bar.sync %0, 128;" :: "r"(wm + 1) : "memory")

__device__ __forceinline__ void mma16(float* c, const uint32_t* a, uint32_t b0, uint32_t b1) {
    asm volatile(
        "mma.sync.aligned.m16n8k16.row.col.f32.f16.f16.f32 "
        "{%0,%1,%2,%3}, {%4,%5,%6,%7}, {%8,%9}, {%0,%1,%2,%3};\n"
        : "+f"(c[0]), "+f"(c[1]), "+f"(c[2]), "+f"(c[3])
        : "r"(a[0]), "r"(a[1]), "r"(a[2]), "r"(a[3]), "r"(b0), "r"(b1));
}

__device__ __forceinline__ void ldsm_x4(uint32_t& r0, uint32_t& r1, uint32_t& r2, uint32_t& r3,
                                        uint32_t addr) {
    asm volatile("ldmatrix.sync.aligned.m8n8.x4.shared.b16 {%0,%1,%2,%3}, [%4];"
                 : "=r"(r0), "=r"(r1), "=r"(r2), "=r"(r3) : "r"(addr));
}

// ---------------- preludes ----------------
__global__ void build_g(const float* __restrict__ fw) {
    int l = blockIdx.x, n = threadIdx.x;
    const float* f = fw + l * 129;
    float acc = f[0] + ((n & 1) ? -f[128] : f[128]);
    float nn = (float)n;
#pragma unroll 4
    for (int k = 1; k < 128; ++k)
        acc += 2.0f * f[k] * cospif((float)k * nn * (1.0f / 128.0f));
    g_dev[l * NMODES + n] = acc * (1.0f / 256.0f);
}

// pair table: t2[l][i] = half2{ g_l[(252-i)&255], g_l[(251-i)&255] }, i<511
__global__ void build_t2() {
    int l = blockIdx.x, i = threadIdx.x + 256 * blockIdx.y;
    if (i >= 512) return;
    uint32_t v = 0;
    if (i < 511) {
        __half lo = __float2half_rn(g_dev[l * NMODES + ((252 - i) & 255)]);
        __half hi = __float2half_rn(g_dev[l * NMODES + ((251 - i) & 255)]);
        __half2 h2 = __halves2half2(lo, hi);
        v = *(const uint32_t*)&h2;
    }
    t2_dev[l * 512 + i] = v;
}

// swizzled W1^T image: element (n, pos*8+jj) <- W1[k=(pos^(n&7))*8+jj][n]
__global__ void build_w1sw(const float* __restrict__ W1) {
    int n = blockIdx.x, j = threadIdx.x;
    int pos = j >> 3, jj = j & 7;
    int k = ((pos ^ (n & 7)) << 3) + jj;
    w1sw_dev[n * 64 + j] = __float2half_rn(W1[k * NMODES + n]);
}

// ---------------- main ----------------
__global__ __launch_bounds__(NTHREADS, 2)
void fno_main(const float* __restrict__ mu, const float* __restrict__ xin,
              const float* __restrict__ b1, const float* __restrict__ lw,
              const float* __restrict__ W2, const float* __restrict__ b2v,
              float* __restrict__ out) {
    extern __shared__ __align__(16) char smem[];
    const uint32_t sb = smem_u32(smem);
    uint32_t* t2s  = (uint32_t*)(smem + T2_OFF);
    float* lw_s    = (float*)(smem + LW_OFF);
    float* b1_s    = (float*)(smem + B1_OFF);
    float* x_s     = (float*)(smem + XS_OFF);
    float* w2_s    = (float*)(smem + W2S_OFF);
    float* dec     = (float*)(smem + DEC_OFF);
    float* hside   = (float*)(smem + HS_OFF);

    const int tid  = threadIdx.x;
    const int lane = tid & 31;
    const int warp = tid >> 5;
    const int lg   = lane >> 2;   // 0..7
    const int tig  = lane & 3;    // 0..3
    const int wm   = warp >> 2;   // 0..1
    const int wn   = warp & 3;    // 0..3
    const size_t row0 = (size_t)blockIdx.x * MROWS;

    // one-shot W1 image copy into bufB region
    {
        const char* src = (const char*)w1sw_dev;
#pragma unroll
        for (int i = 0; i < 8; ++i) {
            int idx = tid + i * NTHREADS;
            CP_ASYNC16(sb + H1_OFF + idx * 16, src + idx * 16);
        }
        CP_COMMIT();
    }

    // tables & small data
    for (int i = tid; i < NLAYERS * 512; i += NTHREADS) t2s[i] = t2_dev[i];
    if (tid < NMODES) b1_s[tid] = b1[tid];
    for (int i = tid; i < NLAYERS * NMODES; i += NTHREADS) lw_s[i] = lw[i];
    for (int i = tid; i < MROWS * 3; i += NTHREADS) {
        int r = i / 3, c = i - r * 3;
        x_s[r * 4 + c] = xin[(row0 + r) * 3 + c];
    }
    if (tid < NMODES) w2_s[tid] = W2[tid];

    // mu -> bufA fp16 words [r][0..31]
    {
        uint32_t* hw0 = (uint32_t*)(smem + H0_OFF);
        for (int i = tid; i < MROWS * 32; i += NTHREADS) {
            int r = i >> 5, w = i & 31;
            float2 v = ((const float2*)(mu + (row0 + r) * 64))[w];
            __half2 h2 = __floats2half2_rn(v.x, v.y);
            hw0[r * HW + w] = *(const uint32_t*)&h2;
        }
    }

    // A ldsm lane row offsets (relative to h buffer base)
    const int a_row = lane & 15;
    const uint32_t a_koff = (uint32_t)((lane >> 4) << 4);
    uint32_t a_rel[2];
#pragma unroll
    for (int mt = 0; mt < 2; ++mt)
        a_rel[mt] = (uint32_t)((wm * 32 + mt * 16 + a_row) * (HW * 4)) + a_koff;

    // W1 (swizzled) ldsm lane offsets (relative to bufB base)
    const int b_nloc = ((lane & 16) >> 1) + (lane & 7);
    const int hi = (lane >> 3) & 1;
    uint32_t w1_off[4];
    int bx[4];
#pragma unroll
    for (int ntp = 0; ntp < 4; ++ntp) {
        int n = wn * 64 + ntp * 16 + b_nloc;
        w1_off[ntp] = (uint32_t)(n << 7);
        bx[ntp] = n & 7;
    }

    // circulant-table per-lane base
    const uint32_t rb0 = sb + T2_OFF + 1020u + 8u * tig - 4u * lg - 256u * wn - 224u;

    // epilogue special lanes (n in 252..255): wn==3, nt==7, tig>=2
    const bool sp_warp = (wn == 3);

    float acc[2][8][4];
#define ZERO_ACC()                                   \
    _Pragma("unroll") for (int mt = 0; mt < 2; ++mt) \
    _Pragma("unroll") for (int nt = 0; nt < 8; ++nt) \
    _Pragma("unroll") for (int j = 0; j < 4; ++j) acc[mt][nt][j] = 0.0f;

    CP_WAIT0();
    __syncthreads();   // W1 image + tables + bufA(mu) visible

    // ---------------- encoder gemm (A = bufA, B = W1 image in bufB) ---------
    ZERO_ACC();
    {
        const uint32_t abase = sb + H0_OFF;
        const uint32_t wbase = sb + H1_OFF;
#pragma unroll
        for (int ks = 0; ks < 4; ++ks) {
            uint32_t a[2][4];
            ldsm_x4(a[0][0], a[0][1], a[0][2], a[0][3], abase + a_rel[0] + ks * 32);
            ldsm_x4(a[1][0], a[1][1], a[1][2], a[1][3], abase + a_rel[1] + ks * 32);
            const int seg = ks * 2 + hi;
#pragma unroll
            for (int ntp = 0; ntp < 4; ++ntp) {
                uint32_t b0, b1r, b2, b3;
                ldsm_x4(b0, b1r, b2, b3,
                        wbase + w1_off[ntp] + (uint32_t)(((seg ^ bx[ntp]) & 7) << 4));
                mma16(acc[0][2 * ntp],     a[0], b0, b1r);
                mma16(acc[1][2 * ntp],     a[1], b0, b1r);
                mma16(acc[0][2 * ntp + 1], a[0], b2, b3);
                mma16(acc[1][2 * ntp + 1], a[1], b2, b3);
            }
        }
    }
    __syncthreads();   // ALL warps done reading W1 before bufB is overwritten

    // encoder epilogue: relu(acc + b1) -> bufB; k-cols 253..255 get x
    {
        uint32_t* hwW = (uint32_t*)(smem + H1_OFF);
#pragma unroll
        for (int mt = 0; mt < 2; ++mt)
#pragma unroll
            for (int half = 0; half < 2; ++half) {
                int r = wm * 32 + mt * 16 + half * 8 + lg;
#pragma unroll
                for (int nt = 0; nt < 8; ++nt) {
                    int n = wn * 64 + nt * 8 + 2 * tig;
                    float2 bv = *(const float2*)(b1_s + n);
                    float v0 = fmaxf(acc[mt][nt][half * 2 + 0] + bv.x, 0.0f);
                    float v1 = fmaxf(acc[mt][nt][half * 2 + 1] + bv.y, 0.0f);
                    if (sp_warp && nt == 7 && tig >= 2) {
                        if (tig == 2) { hside[r * 4 + 0] = v1; v1 = x_s[r * 4 + 0]; }
                        else { hside[r * 4 + 1] = v0; hside[r * 4 + 2] = v1;
                               v0 = x_s[r * 4 + 1]; v1 = x_s[r * 4 + 2]; }
                    }
                    __half2 h2 = __floats2half2_rn(v0, v1);
                    hwW[r * HW + wn * 32 + nt * 4 + tig] = *(const uint32_t*)&h2;
                }
            }
    }
    BAR_GROUP();   // group's new h (bufB) visible within group

    // ---------------- Fourier stages ----------------
    float dsum[4];
#pragma unroll
    for (int s = 0; s < 4; ++s) dsum[s] = 0.0f;

#pragma unroll 1
    for (int l = 1; l <= 4; ++l) {
        const uint32_t roff = (l & 1) ? H1_OFF : H0_OFF;   // read buffer
        const uint32_t woff = (l & 1) ? H0_OFF : H1_OFF;   // write buffer
        uint32_t* hwR = (uint32_t*)(smem + roff);
        uint32_t* hwW = (uint32_t*)(smem + woff);
        ZERO_ACC();
        uint32_t rbv = rb0 + (uint32_t)((l - 1) * 2048);
        uint32_t ra0 = sb + roff + a_rel[0], ra1 = sb + roff + a_rel[1];

        // circular window: v_ks[j] lives in w[(j + 7*ks) % 9]
        // (in-place identity v_{ks+1}[j] = v_ks[j-2] forces slot shift -2 == +7 mod 9)
        uint32_t w[9];
        uint32_t a[2][2][4];
        ldsm_x4(a[0][0][0], a[0][0][1], a[0][0][2], a[0][0][3], ra0);
        ldsm_x4(a[0][1][0], a[0][1][1], a[0][1][2], a[0][1][3], ra1);
        LDS_B(w[0], rbv, 256); LDS_B(w[1], rbv, 224); LDS_B(w[2], rbv, 192);
        LDS_B(w[3], rbv, 160); LDS_B(w[4], rbv, 128); LDS_B(w[5], rbv,  96);
        LDS_B(w[6], rbv,  64); LDS_B(w[7], rbv,  32); LDS_B(w[8], rbv,   0);

#pragma unroll
        for (int ks = 0; ks < 15; ++ks) {
            const int cur = ks & 1, nxt = cur ^ 1;
            ldsm_x4(a[nxt][0][0], a[nxt][0][1], a[nxt][0][2], a[nxt][0][3], ra0 + 32);
            ldsm_x4(a[nxt][1][0], a[nxt][1][1], a[nxt][1][2], a[nxt][1][3], ra1 + 32);
            uint32_t nv0, nv1;
#pragma unroll
            for (int nt = 0; nt < 8; ++nt) {
                const int s0 = (nt + 7 * ks) % 9;
                const int s1 = (nt + 1 + 7 * ks) % 9;
                mma16(acc[0][nt], a[cur][0], w[s1], w[s0]);
                mma16(acc[1][nt], a[cur][1], w[s1], w[s0]);
                if (nt == 2) LDS_B(nv0, rbv, 320);  // v_{ks+1}[0]
                if (nt == 3) LDS_B(nv1, rbv, 288);  // v_{ks+1}[1]
            }
            // commit after slots' last use (v_ks[7], v_ks[8] die at nt=7)
            w[(7 * ks + 7) % 9] = nv0;   // slot(ks+1, 0)
            w[(7 * ks + 8) % 9] = nv1;   // slot(ks+1, 1)
            ra0 += 32; ra1 += 32; rbv += 64;
        }

        // ks = 15: per-nt final MMAs immediately followed by that nt's epilogue
        {
            const float* lws = lw_s + (l - 1) * NMODES;
            const bool last = (l == 4);
#pragma unroll
            for (int nt = 0; nt < 8; ++nt) {
                const int s0 = (nt + 6) % 9;    // (nt + 7*15) % 9
                const int s1 = (nt + 7) % 9;
                mma16(acc[0][nt], a[1][0], w[s1], w[s0]);
                mma16(acc[1][nt], a[1][1], w[s1], w[s0]);

                int n = wn * 64 + nt * 8 + 2 * tig;
                float2 lw2 = *(const float2*)(lws + n);
                const bool sp = sp_warp && nt == 7 && tig >= 2;
#pragma unroll
                for (int mt = 0; mt < 2; ++mt)
#pragma unroll
                    for (int half = 0; half < 2; ++half) {
                        int r = wm * 32 + mt * 16 + half * 8 + lg;
                        const int widx = r * HW + wn * 32 + nt * 4 + tig;
                        uint32_t hraw = hwR[widx];
                        __half2 ho = *(const __half2*)&hraw;
                        float h0f = __low2float(ho);
                        float h1f = __high2float(ho);
                        if (sp) {
                            if (tig == 2) h1f = hside[r * 4 + 0];
                            else { h0f = hside[r * 4 + 1]; h1f = hside[r * 4 + 2]; }
                        }
                        float v0 = fmaxf(acc[mt][nt][half * 2 + 0] + h0f * lw2.x, 0.0f);
                        float v1 = fmaxf(acc[mt][nt][half * 2 + 1] + h1f * lw2.y, 0.0f);
                        if (!last) {
                            if (sp) {
                                if (tig == 2) { hside[r * 4 + 0] = v1; v1 = x_s[r * 4 + 0]; }
                                else { hside[r * 4 + 1] = v0; hside[r * 4 + 2] = v1;
                                       v0 = x_s[r * 4 + 1]; v1 = x_s[r * 4 + 2]; }
                            }
                            __half2 h2 = __floats2half2_rn(v0, v1);
                            hwW[widx] = *(const uint32_t*)&h2;
                        } else {
                            float2 w2v = *(const float2*)(w2_s + n);
                            dsum[mt * 2 + half] += v0 * w2v.x + v1 * w2v.y;
                        }
                    }
            }
        }
        if (l != 4) BAR_GROUP();   // group's new h buffer visible within group
    }

    // ---------------- decoder reduction ----------------
#pragma unroll
    for (int s = 0; s < 4; ++s) {
        dsum[s] += __shfl_xor_sync(0xffffffffu, dsum[s], 1);
        dsum[s] += __shfl_xor_sync(0xffffffffu, dsum[s], 2);
    }
    if (tig == 0) {
#pragma unroll
        for (int s = 0; s < 4; ++s) {
            int mt = s >> 1, half = s & 1;
            int r = wm * 32 + mt * 16 + half * 8 + lg;
            dec[r * 4 + wn] = dsum[s];
        }
    }
    __syncthreads();   // full: dec written by all warps before cross-warp read
    if (tid < MROWS) {
        const float* d = dec + tid * 4;
        out[row0 + tid] = d[0] + d[1] + d[2] + d[3] + b2v[0];
    }
}

// ---------------------------------------------------------------------------
extern "C" void kernel_launch(void* const* d_in, const int* in_sizes, int n_in,
                              void* d_out, int out_size) {
    const float* mu = (const float*)d_in[0];
    const float* x  = (const float*)d_in[1];
    const float* W1 = (const float*)d_in[2];
    const float* b1 = (const float*)d_in[3];
    const float* fw = (const float*)d_in[4];
    const float* lw = (const float*)d_in[5];
    const float* W2 = (const float*)d_in[6];
    const float* b2 = (const float*)d_in[7];
    float* out = (float*)d_out;

    const int B = in_sizes[0] / 64;
    const int nblocks = B / MROWS;

    build_g<<<NLAYERS, NMODES>>>(fw);
    build_t2<<<dim3(NLAYERS, 2), 256>>>();
    build_w1sw<<<NMODES, 64>>>(W1);

    cudaFuncSetAttribute(fno_main, cudaFuncAttributeMaxDynamicSharedMemorySize, SMEM_TOTAL);
    fno_main<<<nblocks, NTHREADS, SMEM_TOTAL>>>(mu, x, b1, lw, W2, b2, out);
}

// round 16
// speedup vs baseline: 1.0268x; 1.0268x over previous
#include <cuda_runtime.h>
#include <cuda_fp16.h>
#include <cstdint>

// ---------------------------------------------------------------------------
// FNO on sm_103a. Circulant Fourier layers via a 2KB reversed-g pair table:
// B[k][n] = g[(n-k-3) mod 256]. Uncropped circulant rows k=253..255 ARE the
// x-term coefficients, so x0..x2 live in h's k-columns 253..255 and the MMA
// computes conv + x-term together. True h[253..255] in a 1KB side array.
//   h0 = relu(mu @ W1 + b1)           (W1 via one-shot cp.async, ldsm path)
//   h  = relu(circ_g([h|x]) + h*lw)   l=0..3
//   out = h @ W2 + b2                 (fused into stage-4 epilogue, fp32)
// R16 = R13 (single h buffer, group barriers) + mod-9 circular B-window:
// slot(ks,j) = (j+7ks)%9 (in-place v_{ks+1}[j]=v_ks[j-2] => shift -2 == +7),
// new values prefetched into temps at nt=2/3, committed after nt=7.
// 256 threads, 64 rows/CTA, 82KB SMEM -> 2 CTAs/SM. No weight streaming.
// ---------------------------------------------------------------------------

#define NMODES 256
#define NLAYERS 4
#define MROWS 64
#define NTHREADS 256
#define HW 132                              // h row stride in 32-bit words
#define H_BYTES (MROWS * HW * 4)            // 33792
#define W1_OFF  H_BYTES                     // 32KB swizzled W1 image
#define T2_OFF  (W1_OFF + 32768)            // 66560: 4 x 2048B pair tables
#define B1_OFF  (T2_OFF + NLAYERS * 2048)   // 74752: b1 (fp32)
#define LW_OFF  (B1_OFF + NMODES * 4)       // 75776: 4x lw (fp32)
#define XS_OFF  (LW_OFF + NLAYERS * NMODES * 4) // 79872
#define W2S_OFF (XS_OFF + MROWS * 4 * 4)    // 80896
#define DEC_OFF (W2S_OFF + NMODES * 4)      // 81920
#define HS_OFF  (DEC_OFF + MROWS * 4 * 4)   // 82944: h[253..255] side (fp32)
#define SMEM_TOTAL (HS_OFF + MROWS * 4 * 4) // 83968

__device__ float g_dev[NLAYERS * NMODES];
__device__ __align__(16) uint32_t t2_dev[NLAYERS * 512]; // half2 pair tables
__device__ __align__(16) __half w1sw_dev[NMODES * 64];   // swizzled W1^T image

__device__ __forceinline__ uint32_t smem_u32(const void* p) {
    uint32_t a;
    asm("{ .reg .u64 t; cvta.to.shared.u64 t, %1; cvt.u32.u64 %0, t; }" : "=r"(a) : "l"(p));
    return a;
}

#define CP_ASYNC16(dst, src) \
    asm volatile("cp.async.cg.shared.global [%0], [%1], 16;" :: "r"(dst), "l"(src) : "memory")
#define CP_COMMIT() asm volatile("cp.async.commit_group;" ::: "memory")
#define CP_WAIT0()  asm volatile("cp.async.wait_group 0;" ::: "memory")

#define LDS_B(dst, base, imm) \
    asm volatile("ld.shared.b32 %0, [%1+%2];" : "=r"(dst) : "r"(base), "n"(imm))

// group barrier: warps 0-3 (wm=0) use barrier 1, warps 4-7 (wm=1) barrier 2
#define BAR_GROUP() \
    asm volatile("bar.sync %0, 128;" :: "r"(wm + 1) : "memory")

__device__ __forceinline__ void mma16(float* c, const uint32_t* a, uint32_t b0, uint32_t b1) {
    asm volatile(
        "mma.sync.aligned.m16n8k16.row.col.f32.f16.f16.f32 "
        "{%0,%1,%2,%3}, {%4,%5,%6,%7}, {%8,%9}, {%0,%1,%2,%3};\n"
        : "+f"(c[0]), "+f"(c[1]), "+f"(c[2]), "+f"(c[3])
        : "r"(a[0]), "r"(a[1]), "r"(a[2]), "r"(a[3]), "r"(b0), "r"(b1));
}

__device__ __forceinline__ void ldsm_x4(uint32_t& r0, uint32_t& r1, uint32_t& r2, uint32_t& r3,
                                        uint32_t addr) {
    asm volatile("ldmatrix.sync.aligned.m8n8.x4.shared.b16 {%0,%1,%2,%3}, [%4];"
                 : "=r"(r0), "=r"(r1), "=r"(r2), "=r"(r3) : "r"(addr));
}

// ---------------- preludes ----------------
__global__ void build_g(const float* __restrict__ fw) {
    int l = blockIdx.x, n = threadIdx.x;
    const float* f = fw + l * 129;
    float acc = f[0] + ((n & 1) ? -f[128] : f[128]);
    float nn = (float)n;
#pragma unroll 4
    for (int k = 1; k < 128; ++k)
        acc += 2.0f * f[k] * cospif((float)k * nn * (1.0f / 128.0f));
    g_dev[l * NMODES + n] = acc * (1.0f / 256.0f);
}

// pair table: t2[l][i] = half2{ g_l[(252-i)&255], g_l[(251-i)&255] }, i<511
__global__ void build_t2() {
    int l = blockIdx.x, i = threadIdx.x + 256 * blockIdx.y;
    if (i >= 512) return;
    uint32_t v = 0;
    if (i < 511) {
        __half lo = __float2half_rn(g_dev[l * NMODES + ((252 - i) & 255)]);
        __half hi = __float2half_rn(g_dev[l * NMODES + ((251 - i) & 255)]);
        __half2 h2 = __halves2half2(lo, hi);
        v = *(const uint32_t*)&h2;
    }
    t2_dev[l * 512 + i] = v;
}

// swizzled W1^T image: element (n, pos*8+jj) <- W1[k=(pos^(n&7))*8+jj][n]
__global__ void build_w1sw(const float* __restrict__ W1) {
    int n = blockIdx.x, j = threadIdx.x;
    int pos = j >> 3, jj = j & 7;
    int k = ((pos ^ (n & 7)) << 3) + jj;
    w1sw_dev[n * 64 + j] = __float2half_rn(W1[k * NMODES + n]);
}

// ---------------- main ----------------
__global__ __launch_bounds__(NTHREADS, 2)
void fno_main(const float* __restrict__ mu, const float* __restrict__ xin,
              const float* __restrict__ b1, const float* __restrict__ lw,
              const float* __restrict__ W2, const float* __restrict__ b2v,
              float* __restrict__ out) {
    extern __shared__ __align__(16) char smem[];
    const uint32_t sb = smem_u32(smem);
    uint32_t* hw   = (uint32_t*)smem;
    uint32_t* t2s  = (uint32_t*)(smem + T2_OFF);
    float* b1_s    = (float*)(smem + B1_OFF);
    float* lw_s    = (float*)(smem + LW_OFF);
    float* x_s     = (float*)(smem + XS_OFF);
    float* w2_s    = (float*)(smem + W2S_OFF);
    float* dec     = (float*)(smem + DEC_OFF);
    float* hside   = (float*)(smem + HS_OFF);

    const int tid  = threadIdx.x;
    const int lane = tid & 31;
    const int warp = tid >> 5;
    const int lg   = lane >> 2;   // 0..7
    const int tig  = lane & 3;    // 0..3
    const int wm   = warp >> 2;   // 0..1
    const int wn   = warp & 3;    // 0..3
    const size_t row0 = (size_t)blockIdx.x * MROWS;

    // one-shot W1 image copy
    {
        const char* src = (const char*)w1sw_dev;
#pragma unroll
        for (int i = 0; i < 8; ++i) {
            int idx = tid + i * NTHREADS;
            CP_ASYNC16(sb + W1_OFF + idx * 16, src + idx * 16);
        }
        CP_COMMIT();
    }

    // tables & small data
    for (int i = tid; i < NLAYERS * 512; i += NTHREADS) t2s[i] = t2_dev[i];
    if (tid < NMODES) b1_s[tid] = b1[tid];
    for (int i = tid; i < NLAYERS * NMODES; i += NTHREADS) lw_s[i] = lw[i];
    for (int i = tid; i < MROWS * 3; i += NTHREADS) {
        int r = i / 3, c = i - r * 3;
        x_s[r * 4 + c] = xin[(row0 + r) * 3 + c];
    }
    if (tid < NMODES) w2_s[tid] = W2[tid];

    // mu -> h fp16 words [r][0..31]
    for (int i = tid; i < MROWS * 32; i += NTHREADS) {
        int r = i >> 5, w = i & 31;
        float2 v = ((const float2*)(mu + (row0 + r) * 64))[w];
        __half2 h2 = __floats2half2_rn(v.x, v.y);
        hw[r * HW + w] = *(const uint32_t*)&h2;
    }

    // A ldsm lane bases
    const int a_row = lane & 15;
    const uint32_t a_koff = (uint32_t)((lane >> 4) << 4);
    uint32_t a_base[2];
#pragma unroll
    for (int mt = 0; mt < 2; ++mt)
        a_base[mt] = sb + (wm * 32 + mt * 16 + a_row) * (HW * 4) + a_koff;

    // W1 (swizzled) ldsm lane bases
    const int b_nloc = ((lane & 16) >> 1) + (lane & 7);
    const int hi = (lane >> 3) & 1;
    uint32_t w1_off[4];
    int bx[4];
#pragma unroll
    for (int ntp = 0; ntp < 4; ++ntp) {
        int n = wn * 64 + ntp * 16 + b_nloc;
        w1_off[ntp] = (uint32_t)(n << 7);
        bx[ntp] = n & 7;
    }

    // circulant-table per-lane base
    const uint32_t rb0 = sb + T2_OFF + 1020u + 8u * tig - 4u * lg - 256u * wn - 224u;

    // epilogue special lanes (n in 252..255): wn==3, nt==7, tig>=2
    const bool sp_warp = (wn == 3);

    float acc[2][8][4];
#define ZERO_ACC()                                   \
    _Pragma("unroll") for (int mt = 0; mt < 2; ++mt) \
    _Pragma("unroll") for (int nt = 0; nt < 8; ++nt) \
    _Pragma("unroll") for (int j = 0; j < 4; ++j) acc[mt][nt][j] = 0.0f;

    CP_WAIT0();
    __syncthreads();   // full: W1 image + tables + h0 visible to everyone

    // ---------------- encoder gemm (K=64, W1 image via ldsm) ----------------
    ZERO_ACC();
    {
        const uint32_t wbase = sb + W1_OFF;
#pragma unroll
        for (int ks = 0; ks < 4; ++ks) {
            uint32_t a[2][4];
            ldsm_x4(a[0][0], a[0][1], a[0][2], a[0][3], a_base[0] + ks * 32);
            ldsm_x4(a[1][0], a[1][1], a[1][2], a[1][3], a_base[1] + ks * 32);
            const int seg = ks * 2 + hi;
#pragma unroll
            for (int ntp = 0; ntp < 4; ++ntp) {
                uint32_t b0, b1r, b2, b3;
                ldsm_x4(b0, b1r, b2, b3,
                        wbase + w1_off[ntp] + (uint32_t)(((seg ^ bx[ntp]) & 7) << 4));
                mma16(acc[0][2 * ntp],     a[0], b0, b1r);
                mma16(acc[1][2 * ntp],     a[1], b0, b1r);
                mma16(acc[0][2 * ntp + 1], a[0], b2, b3);
                mma16(acc[1][2 * ntp + 1], a[1], b2, b3);
            }
        }
    }
    BAR_GROUP();   // group's h rows fully read by group's warps
    // encoder epilogue: relu(acc + b1) -> h; k-cols 253..255 get x, true h -> hside
#pragma unroll
    for (int mt = 0; mt < 2; ++mt)
#pragma unroll
        for (int half = 0; half < 2; ++half) {
            int r = wm * 32 + mt * 16 + half * 8 + lg;
#pragma unroll
            for (int nt = 0; nt < 8; ++nt) {
                int n = wn * 64 + nt * 8 + 2 * tig;
                float2 bv = *(const float2*)(b1_s + n);
                float v0 = fmaxf(acc[mt][nt][half * 2 + 0] + bv.x, 0.0f);
                float v1 = fmaxf(acc[mt][nt][half * 2 + 1] + bv.y, 0.0f);
                if (sp_warp && nt == 7 && tig >= 2) {
                    if (tig == 2) { hside[r * 4 + 0] = v1; v1 = x_s[r * 4 + 0]; }
                    else { hside[r * 4 + 1] = v0; hside[r * 4 + 2] = v1;
                           v0 = x_s[r * 4 + 1]; v1 = x_s[r * 4 + 2]; }
                }
                __half2 h2 = __floats2half2_rn(v0, v1);
                hw[r * HW + wn * 32 + nt * 4 + tig] = *(const uint32_t*)&h2;
            }
        }
    BAR_GROUP();   // group's new h visible within group

    // ---------------- Fourier stages ----------------
    float dsum[4];
#pragma unroll
    for (int s = 0; s < 4; ++s) dsum[s] = 0.0f;

#pragma unroll 1
    for (int l = 1; l <= 4; ++l) {
        ZERO_ACC();
        uint32_t rbv = rb0 + (uint32_t)((l - 1) * 2048);
        uint32_t ra0 = a_base[0], ra1 = a_base[1];

        // circular window: v_ks[j] lives in w[(j + 7*ks) % 9]
        // (in-place v_{ks+1}[j] = v_ks[j-2] forces slot shift -2 == +7 mod 9)
        uint32_t w[9];
        uint32_t a[2][2][4];
        ldsm_x4(a[0][0][0], a[0][0][1], a[0][0][2], a[0][0][3], ra0);
        ldsm_x4(a[0][1][0], a[0][1][1], a[0][1][2], a[0][1][3], ra1);
        LDS_B(w[0], rbv, 256); LDS_B(w[1], rbv, 224); LDS_B(w[2], rbv, 192);
        LDS_B(w[3], rbv, 160); LDS_B(w[4], rbv, 128); LDS_B(w[5], rbv,  96);
        LDS_B(w[6], rbv,  64); LDS_B(w[7], rbv,  32); LDS_B(w[8], rbv,   0);

#pragma unroll
        for (int ks = 0; ks < 16; ++ks) {
            const int cur = ks & 1, nxt = cur ^ 1;
            if (ks < 15) {
                ldsm_x4(a[nxt][0][0], a[nxt][0][1], a[nxt][0][2], a[nxt][0][3], ra0 + 32);
                ldsm_x4(a[nxt][1][0], a[nxt][1][1], a[nxt][1][2], a[nxt][1][3], ra1 + 32);
            }
            uint32_t nv0, nv1;
#pragma unroll
            for (int nt = 0; nt < 8; ++nt) {
                const int s0 = (nt + 7 * ks) % 9;
                const int s1 = (nt + 1 + 7 * ks) % 9;
                mma16(acc[0][nt], a[cur][0], w[s1], w[s0]);
                mma16(acc[1][nt], a[cur][1], w[s1], w[s0]);
                if (ks < 15) {
                    if (nt == 2) LDS_B(nv0, rbv, 320);  // v_{ks+1}[0]
                    if (nt == 3) LDS_B(nv1, rbv, 288);  // v_{ks+1}[1]
                }
            }
            if (ks < 15) {
                // commit after slots' last use (v_ks[7], v_ks[8] die at nt=7)
                w[(7 * ks + 7) % 9] = nv0;   // slot(ks+1, 0)
                w[(7 * ks + 8) % 9] = nv1;   // slot(ks+1, 1)
                ra0 += 32; ra1 += 32; rbv += 64;
            }
        }

        BAR_GROUP();   // group's h rows fully read

        const float* lws = lw_s + (l - 1) * NMODES;
        const bool last = (l == 4);
#pragma unroll
        for (int mt = 0; mt < 2; ++mt)
#pragma unroll
            for (int half = 0; half < 2; ++half) {
                int r = wm * 32 + mt * 16 + half * 8 + lg;
#pragma unroll
                for (int nt = 0; nt < 8; ++nt) {
                    int n = wn * 64 + nt * 8 + 2 * tig;
                    const int widx = r * HW + wn * 32 + nt * 4 + tig;
                    uint32_t hraw = hw[widx];
                    __half2 ho = *(const __half2*)&hraw;
                    float h0f = __low2float(ho);
                    float h1f = __high2float(ho);
                    const bool sp = sp_warp && nt == 7 && tig >= 2;
                    if (sp) {
                        if (tig == 2) h1f = hside[r * 4 + 0];
                        else { h0f = hside[r * 4 + 1]; h1f = hside[r * 4 + 2]; }
                    }
                    float2 lw2 = *(const float2*)(lws + n);
                    float v0 = fmaxf(acc[mt][nt][half * 2 + 0] + h0f * lw2.x, 0.0f);
                    float v1 = fmaxf(acc[mt][nt][half * 2 + 1] + h1f * lw2.y, 0.0f);
                    if (!last) {
                        if (sp) {
                            if (tig == 2) { hside[r * 4 + 0] = v1; v1 = x_s[r * 4 + 0]; }
                            else { hside[r * 4 + 1] = v0; hside[r * 4 + 2] = v1;
                                   v0 = x_s[r * 4 + 1]; v1 = x_s[r * 4 + 2]; }
                        }
                        __half2 h2 = __floats2half2_rn(v0, v1);
                        hw[widx] = *(const uint32_t*)&h2;
                    } else {
                        float2 w2v = *(const float2*)(w2_s + n);
                        dsum[mt * 2 + half] += v0 * w2v.x + v1 * w2v.y;
                    }
                }
            }
        if (!last) BAR_GROUP();   // group's new h visible within group
    }

    // ---------------- decoder reduction ----------------
#pragma unroll
    for (int s = 0; s < 4; ++s) {
        dsum[s] += __shfl_xor_sync(0xffffffffu, dsum[s], 1);
        dsum[s] += __shfl_xor_sync(0xffffffffu, dsum[s], 2);
    }
    if (tig == 0) {
#pragma unroll
        for (int s = 0; s < 4; ++s) {
            int mt = s >> 1, half = s & 1;
            int r = wm * 32 + mt * 16 + half * 8 + lg;
            dec[r * 4 + wn] = dsum[s];
        }
    }
    __syncthreads();   // full: dec written by all warps before cross-warp read
    if (tid < MROWS) {
        const float* d = dec + tid * 4;
        out[row0 + tid] = d[0] + d[1] + d[2] + d[3] + b2v[0];
    }
}

// ---------------------------------------------------------------------------
extern "C" void kernel_launch(void* const* d_in, const int* in_sizes, int n_in,
                              void* d_out, int out_size) {
    const float* mu = (const float*)d_in[0];
    const float* x  = (const float*)d_in[1];
    const float* W1 = (const float*)d_in[2];
    const float* b1 = (const float*)d_in[3];
    const float* fw = (const float*)d_in[4];
    const float* lw = (const float*)d_in[5];
    const float* W2 = (const float*)d_in[6];
    const float* b2 = (const float*)d_in[7];
    float* out = (float*)d_out;

    const int B = in_sizes[0] / 64;
    const int nblocks = B / MROWS;

    build_g<<<NLAYERS, NMODES>>>(fw);
    build_t2<<<dim3(NLAYERS, 2), 256>>>();
    build_w1sw<<<NMODES, 64>>>(W1);

    cudaFuncSetAttribute(fno_main, cudaFuncAttributeMaxDynamicSharedMemorySize, SMEM_TOTAL);
    fno_main<<<nblocks, NTHREADS, SMEM_TOTAL>>>(mu, x, b1, lw, W2, b2, out);
}